// round 11
// baseline (speedup 1.0000x reference)
#include <cuda_runtime.h>
#include <cstdint>

// Problem constants
#define LD      64
#define HWD     4096
#define NROWS   65536
#define KCODES  1024
#define ELEMS   4194304
#define LPAD    136         // padded stride (words) -> conflict-free fragment LDS
#define NSLOT   6           // candidate slots per (row, tg) owner
#define TAU     2e-3f       // screening slack; bf16 worst-case error ~1.3e-3

// Scratch (static device allocations only)
__device__ int    g_idx[NROWS];
__device__ float  g_en2[KCODES];
__device__ double g_loss;

__device__ __forceinline__ unsigned pack_bf2(float lo, float hi) {
    unsigned r;
    asm("cvt.rn.bf16x2.f32 %0, %1, %2;" : "=r"(r) : "f"(hi), "f"(lo));
    return r;
}

// Warp-level bf16 MMA, D(16x8,f32) += A(16x16) * B(16x8)
#define MMA_BF16(c0,c1,c2,c3, a0,a1,a2,a3, b0,b1) \
    asm volatile("mma.sync.aligned.m16n8k16.row.col.f32.bf16.bf16.f32 " \
        "{%0,%1,%2,%3}, {%4,%5,%6,%7}, {%8,%9}, {%0,%1,%2,%3};" \
        : "+f"(c0), "+f"(c1), "+f"(c2), "+f"(c3) \
        : "r"(a0), "r"(a1), "r"(a2), "r"(a3), "r"(b0), "r"(b1))

// ---------------------------------------------------------------------------
// K1: exact per-code squared norms (separate mul/add, sequential order —
// matches jnp.sum(emb*emb, axis=1) bit-exactly). Zeroes loss accumulator.
// ---------------------------------------------------------------------------
__global__ void en2_kernel(const float* __restrict__ emb) {
    int k = blockIdx.x * blockDim.x + threadIdx.x;
    if (k == 0) g_loss = 0.0;
    if (k < KCODES) {
        const float* e = emb + k * LD;
        float s = 0.0f;
#pragma unroll
        for (int l = 0; l < LD; l++)
            s = __fadd_rn(s, __fmul_rn(e[l], e[l]));
        g_en2[k] = s;
    }
}

// ---------------------------------------------------------------------------
// K2: bf16 mma.sync screen with REGISTER-LOCAL candidate collection
//     (no atomics, no threshold exchange) + bit-exact fp32 recheck.
//   Block = 128 rows, 128 threads, 4 warps x 32 rows. Each thread owns rows
//   {r0..r3} and codes congruent to {2tg, 2tg+1} mod 8. Thread-local running
//   min + candidate slots; threshold local_min + TAU >= global_min + TAU
//   -> strictly over-collects vs the proven criterion. Overflow (>NSLOT) ->
//   exact scan of that owner's 256-code subset. Exact fp32 phase decides.
// ---------------------------------------------------------------------------
__global__ void __launch_bounds__(128, 4)
screen_kernel(const float* __restrict__ ze, const float* __restrict__ emb,
              float* __restrict__ out_idx) {
    // szb region is dead after fragment hoist -> aliased to cand/counts.
    __shared__ unsigned s_region1[32 * LPAD];          // szb | cand+counts
    __shared__ unsigned s_scb[32 * LPAD];              // bf16x2 code tile
    __shared__ float    s_en2[KCODES];                 // exact ||e||^2 (all)

    unsigned* szb    = s_region1;
    int*      cand   = (int*)s_region1;                // [128][4][NSLOT]
    int*      counts = (int*)s_region1 + 128 * 4 * NSLOT;  // [128][4]

    const int tid  = threadIdx.x;
    const int lane = tid & 31, wid = tid >> 5;
    const int rowbase = blockIdx.x * 128;
    const int b   = rowbase >> 12;          // all 128 rows share batch b
    const int hw0 = rowbase & 4095;

    // Load zf (thread = row): pack bf16x2 pairs to szb, and compute
    // a = ||zf||^2 in exact sequential order (l = 0..63) into a register.
    const float* zrow = ze + ((size_t)(b * LD) << 12) + hw0 + tid;
    float a = 0.0f;
#pragma unroll
    for (int l2 = 0; l2 < 32; l2++) {
        float f0 = zrow[(size_t)(2 * l2    ) << 12];
        float f1 = zrow[(size_t)(2 * l2 + 1) << 12];
        a = __fadd_rn(a, __fmul_rn(f0, f0));
        a = __fadd_rn(a, __fmul_rn(f1, f1));
        szb[l2 * LPAD + tid] = pack_bf2(f0, f1);
    }
    for (int i = tid; i < KCODES; i += 128) s_en2[i] = g_en2[i];
    __syncthreads();

    // Warp tiling: warp covers rows mb..mb+31, all 128 codes of each tile.
    const int mb = wid << 5;
    const int q  = lane >> 2;          // 0..7
    const int tg = lane & 3;           // 0..3
    const int r0 = mb + q;             // rows r0, r0+8, r0+16, r0+24

    // Hoist A fragments (invariant across all code tiles): 4 ks x 8 regs.
    unsigned Af[4][8];
#pragma unroll
    for (int ks = 0; ks < 4; ks++) {
        int p = ks * 8 + tg;
        Af[ks][0] = szb[(p    ) * LPAD + r0];
        Af[ks][1] = szb[(p    ) * LPAD + r0 + 8];
        Af[ks][2] = szb[(p + 4) * LPAD + r0];
        Af[ks][3] = szb[(p + 4) * LPAD + r0 + 8];
        Af[ks][4] = szb[(p    ) * LPAD + r0 + 16];
        Af[ks][5] = szb[(p    ) * LPAD + r0 + 24];
        Af[ks][6] = szb[(p + 4) * LPAD + r0 + 16];
        Af[ks][7] = szb[(p + 4) * LPAD + r0 + 24];
    }
    __syncthreads();   // szb dead; region1 becomes cand/counts

    // Thread-local screening state (registers only)
    float runmin[4];
    int   cnt[4];
#pragma unroll
    for (int r = 0; r < 4; r++) {
        runmin[r] = __int_as_float(0x7f800000);
        cnt[r] = 0;
    }

    for (int ct = 0; ct < 8; ct++) {
        if (ct) __syncthreads();       // all warps done with previous tile
        // Load code tile: thread = code c (1 of 128). Conflict-free STS.
        {
            const float4* src = (const float4*)(emb +
                                ((size_t)(ct * 128 + tid)) * LD);
#pragma unroll
            for (int j = 0; j < 16; j++) {
                float4 v = src[j];
                s_scb[(2 * j    ) * LPAD + tid] = pack_bf2(v.x, v.y);
                s_scb[(2 * j + 1) * LPAD + tid] = pack_bf2(v.z, v.w);
            }
        }
        __syncthreads();

        // 8 chunks of 2 ns: acc live range 16 regs.
#pragma unroll
        for (int chunk = 0; chunk < 8; chunk++) {
            float acc[2][8];
#pragma unroll
            for (int nsl = 0; nsl < 2; nsl++)
#pragma unroll
                for (int j = 0; j < 8; j++) acc[nsl][j] = 0.0f;

#pragma unroll
            for (int ks = 0; ks < 4; ks++) {
                int p = ks * 8 + tg;
#pragma unroll
                for (int nsl = 0; nsl < 2; nsl++) {
                    int cb = (chunk * 2 + nsl) * 8;
                    unsigned b0 = s_scb[(p    ) * LPAD + cb + q];
                    unsigned b1 = s_scb[(p + 4) * LPAD + cb + q];
                    MMA_BF16(acc[nsl][0], acc[nsl][1], acc[nsl][2], acc[nsl][3],
                             Af[ks][0], Af[ks][1], Af[ks][2], Af[ks][3], b0, b1);
                    MMA_BF16(acc[nsl][4], acc[nsl][5], acc[nsl][6], acc[nsl][7],
                             Af[ks][4], Af[ks][5], Af[ks][6], Af[ks][7], b0, b1);
                }
            }

            // Register-local epilogue: s~ = en2 - 2 m~, local min + collect.
#pragma unroll
            for (int nsl = 0; nsl < 2; nsl++) {
                int cl = (chunk * 2 + nsl) * 8 + 2 * tg;
                int k0 = ct * 128 + cl;
                float e0 = s_en2[k0], e1 = s_en2[k0 + 1];
#pragma unroll
                for (int j = 0; j < 8; j++) {
                    int   ridx = j >> 1;
                    int   k    = k0 + (j & 1);
                    float s    = ((j & 1) ? e1 : e0) - 2.0f * acc[nsl][j];
                    if (s < runmin[ridx]) runmin[ridx] = s;
                    if (s <= runmin[ridx] + TAU) {
                        if (cnt[ridx] < NSLOT) {
                            int row = r0 + 8 * ridx;
                            cand[(row * 4 + tg) * NSLOT + cnt[ridx]] = k;
                        }
                        cnt[ridx]++;
                    }
                }
            }
        }
    }

    // Publish counts (statically owned slots, no atomics).
#pragma unroll
    for (int ridx = 0; ridx < 4; ridx++)
        counts[(r0 + 8 * ridx) * 4 + tg] = cnt[ridx];
    __syncthreads();

    // Exact phase: thread = row. Replays bit-exact reference arithmetic on
    // the union of the 4 owners' candidate lists (overflow -> owner-subset
    // exact scan). zf reloaded from gmem (L1/L2-hot, coalesced per l).
    {
        float best = __int_as_float(0x7f800000);
        int   bi   = 0;
#pragma unroll
        for (int tg_ = 0; tg_ < 4; tg_++) {
            int c_ = counts[tid * 4 + tg_];
            if (c_ <= NSLOT) {
                for (int j = 0; j < c_; j++) {
                    int k = cand[(tid * 4 + tg_) * NSLOT + j];
                    const float* e = emb + (size_t)k * LD;
                    float m = 0.0f;
#pragma unroll
                    for (int l = 0; l < LD; l++)
                        m = __fmaf_rn(zrow[(size_t)l << 12], __ldg(e + l), m);
                    float d = __fadd_rn(__fadd_rn(a, s_en2[k]),
                                        __fmul_rn(-2.0f, m));
                    if (d < best || (d == best && k < bi)) { best = d; bi = k; }
                }
            } else {
                // Overflow: exact scan of this owner's 256-code subset.
                for (int ct = 0; ct < 8; ct++)
                    for (int ns = 0; ns < 16; ns++)
                        for (int jj = 0; jj < 2; jj++) {
                            int k = ct * 128 + ns * 8 + 2 * tg_ + jj;
                            const float* e = emb + (size_t)k * LD;
                            float m = 0.0f;
#pragma unroll
                            for (int l = 0; l < LD; l++)
                                m = __fmaf_rn(zrow[(size_t)l << 12],
                                              __ldg(e + l), m);
                            float d = __fadd_rn(__fadd_rn(a, s_en2[k]),
                                                __fmul_rn(-2.0f, m));
                            if (d < best || (d == best && k < bi)) {
                                best = d; bi = k;
                            }
                        }
            }
        }
        int n = rowbase + tid;
        g_idx[n]   = bi;
        out_idx[n] = (float)bi;
    }
}

// ---------------------------------------------------------------------------
// K3: gather z_q (float4), z_q_st = ze + (z_q - ze) in reference op order,
// block-reduce fl32((z_q-ze)^2) in double, one atomicAdd per block.
// ---------------------------------------------------------------------------
__global__ void __launch_bounds__(256)
gather_kernel(const float* __restrict__ ze, const float* __restrict__ emb,
              float* __restrict__ out) {
    __shared__ double swarp[8];
    int i   = (blockIdx.x * 256 + threadIdx.x) * 4;
    int b   = i >> 18;
    int rem = i & 262143;
    int l   = rem >> 12;
    int hw  = rem & 4095;
    int n   = (b << 12) | hw;

    int4   ki  = *(const int4*)(g_idx + n);
    float4 ze4 = *(const float4*)(ze + i);
    float t0 = __fadd_rn(emb[ki.x * LD + l], -ze4.x);
    float t1 = __fadd_rn(emb[ki.y * LD + l], -ze4.y);
    float t2 = __fadd_rn(emb[ki.z * LD + l], -ze4.z);
    float t3 = __fadd_rn(emb[ki.w * LD + l], -ze4.w);
    float4 o4;
    o4.x = __fadd_rn(ze4.x, t0);
    o4.y = __fadd_rn(ze4.y, t1);
    o4.z = __fadd_rn(ze4.z, t2);
    o4.w = __fadd_rn(ze4.w, t3);
    *(float4*)(out + i) = o4;

    double s = (double)__fmul_rn(t0, t0) + (double)__fmul_rn(t1, t1)
             + (double)__fmul_rn(t2, t2) + (double)__fmul_rn(t3, t3);
#pragma unroll
    for (int o = 16; o > 0; o >>= 1)
        s += __shfl_down_sync(0xffffffffu, s, o);
    int w = threadIdx.x >> 5, lid = threadIdx.x & 31;
    if (lid == 0) swarp[w] = s;
    __syncthreads();
    if (w == 0) {
        double v = (lid < 8) ? swarp[lid] : 0.0;
#pragma unroll
        for (int o = 4; o > 0; o >>= 1)
            v += __shfl_down_sync(0xffffffffu, v, o);
        if (lid == 0) atomicAdd(&g_loss, v);
    }
}

__global__ void loss_kernel(float* __restrict__ out) {
    out[ELEMS] = (float)(g_loss / (double)ELEMS * 1.25);
}

// ---------------------------------------------------------------------------
// Launch. Outputs: [z_q_st (4194304)] [loss (1)] [idx (65536)]
// ---------------------------------------------------------------------------
extern "C" void kernel_launch(void* const* d_in, const int* in_sizes, int n_in,
                              void* d_out, int out_size) {
    const float* ze  = (const float*)d_in[0];
    const float* emb = (const float*)d_in[1];
    float* out     = (float*)d_out;
    float* out_idx = out + ELEMS + 1;

    en2_kernel   <<<(KCODES + 255) / 256, 256>>>(emb);
    screen_kernel<<<NROWS / 128, 128>>>(ze, emb, out_idx);
    gather_kernel<<<ELEMS / (256 * 4), 256>>>(ze, emb, out);
    loss_kernel  <<<1, 1>>>(out);
}

// round 13
// speedup vs baseline: 4.0628x; 4.0628x over previous
#include <cuda_runtime.h>
#include <cstdint>

// Problem constants
#define LD      64
#define HWD     4096
#define NROWS   65536
#define KCODES  1024
#define ELEMS   4194304

typedef unsigned long long u64;

// Scratch (static device allocations only)
__device__ int    g_idx[NROWS];
__device__ float  g_en2[KCODES];
__device__ double g_loss;

// Packed fp32x2 FMA: two independent rn fp32 FMAs — bit-identical per lane
// to scalar __fmaf_rn (proven rel_err 0.0 in R4/R5).
#define FMA2(d, a, b) \
    asm("fma.rn.f32x2 %0, %1, %2, %0;" : "+l"(d) : "l"(a), "l"(b))
__device__ __forceinline__ u64 pk2(float lo, float hi) {
    u64 r;
    asm("mov.b64 %0, {%1, %2};" : "=l"(r) : "f"(lo), "f"(hi));
    return r;
}
#define UNPK2(lo, hi, in) \
    asm("mov.b64 {%0, %1}, %2;" : "=f"(lo), "=f"(hi) : "l"(in))

// ---------------------------------------------------------------------------
// K1: exact per-code squared norms (separate mul/add, sequential order —
// matches jnp.sum(emb*emb, axis=1) bit-exactly). Zeroes loss accumulator.
// ---------------------------------------------------------------------------
__global__ void en2_kernel(const float* __restrict__ emb) {
    int k = blockIdx.x * blockDim.x + threadIdx.x;
    if (k == 0) g_loss = 0.0;
    if (k < KCODES) {
        const float* e = emb + k * LD;
        float s = 0.0f;
#pragma unroll
        for (int l = 0; l < LD; l++)
            s = __fadd_rn(s, __fmul_rn(e[l], e[l]));
        g_en2[k] = s;
    }
}

// ---------------------------------------------------------------------------
// K2: exact FFMA2 register-blocked argmin GEMM. No screening, no approx.
//   Block = 128 rows, 256 threads. Thread = (rg, cg): 4 rows x 4 code-pairs
//   per chunk -> 16 independent f32x2 chains (each the exact sequential
//   reference fp32 FMA chain). d = fl(fl(a + en2) - 2m), guarded first-min.
// ---------------------------------------------------------------------------
#define OFF_ZD   0                    // u64 [64][128]  (z,z) pairs   64 KB
#define OFF_CT   65536                // u64 [64][8][8] code pairs    32 KB
#define OFF_EN2  (65536 + 32768)      // float[1024]                   4 KB
#define OFF_SA   (OFF_EN2 + 4096)     // float[128]                  0.5 KB
#define SMEM_ARG (OFF_SA + 512)
// reduction buffers alias ctile (dead after main loop, fenced by syncs)
#define OFF_RD   OFF_CT               // float[128][8]
#define OFF_RK   (OFF_CT + 4096)      // int[128][8]

__global__ void __launch_bounds__(256, 2)
argmin_kernel(const float* __restrict__ ze, const float* __restrict__ emb,
              float* __restrict__ out_idx) {
    extern __shared__ unsigned char sm[];
    u64*   zdup  = (u64*)(sm + OFF_ZD);
    u64*   ctile = (u64*)(sm + OFF_CT);
    float* sen2  = (float*)(sm + OFF_EN2);
    float* sa    = (float*)(sm + OFF_SA);

    const int tid = threadIdx.x;
    const int cg  = tid & 7;          // code-group 0..7
    const int rg  = tid >> 3;         // row-group 0..31 (rows 4rg..4rg+3)
    const int rowbase = blockIdx.x * 128;
    const int b   = rowbase >> 12;    // all 128 rows share batch b
    const int hw0 = rowbase & 4095;

    // Fill zdup: thread (r = tid&127, half = tid>>7), coalesced LDG per l.
    {
        int r = tid & 127, h = tid >> 7;
        const float* zc = ze + ((size_t)(b * LD + 32 * h) << 12) + hw0 + r;
#pragma unroll
        for (int l = 0; l < 32; l++) {
            float f = zc[(size_t)l << 12];
            zdup[(32 * h + l) * 128 + r] = pk2(f, f);
        }
    }
    for (int i = tid; i < KCODES; i += 256) sen2[i] = g_en2[i];
    __syncthreads();

    // a[r] = ||zf_r||^2, exact sequential order l = 0..63 (mul+add rounding).
    if (tid < 128) {
        const float* zcol = (const float*)(zdup + tid);   // lo word of (z,z)
        float a = 0.0f;
#pragma unroll
        for (int l = 0; l < LD; l++) {
            float v = zcol[l * 256];                      // u64 stride = 2 floats
            a = __fadd_rn(a, __fmul_rn(v, v));
        }
        sa[tid] = a;
    }
    __syncthreads();

    float a_g[4];
#pragma unroll
    for (int g = 0; g < 4; g++) a_g[g] = sa[4 * rg + g];

    float best[4];
    int   bi[4];
#pragma unroll
    for (int g = 0; g < 4; g++) {
        best[g] = __int_as_float(0x7f800000);
        bi[g]   = 0;
    }

    for (int ct = 0; ct < 8; ct++) {
        __syncthreads();   // previous tile fully consumed
        // Load code tile: pair p = (codes 2p, 2p+1), layout [l][jj][cg],
        // jj = p&7, cgp = p>>3. Thread (p = tid&63, qtr = tid>>6) does 16 l's.
        {
            int p = tid & 63, qtr = tid >> 6;
            int jj = p & 7, cgp = p >> 3;
            const float4* e0 = (const float4*)(emb +
                               ((size_t)(ct * 128 + 2 * p)) * LD + qtr * 16);
            const float4* e1 = (const float4*)(emb +
                               ((size_t)(ct * 128 + 2 * p + 1)) * LD + qtr * 16);
#pragma unroll
            for (int v = 0; v < 4; v++) {
                float4 x = e0[v];
                float4 y = e1[v];
                int lb = qtr * 16 + v * 4;
                ctile[((lb + 0) * 8 + jj) * 8 + cgp] = pk2(x.x, y.x);
                ctile[((lb + 1) * 8 + jj) * 8 + cgp] = pk2(x.y, y.y);
                ctile[((lb + 2) * 8 + jj) * 8 + cgp] = pk2(x.z, y.z);
                ctile[((lb + 3) * 8 + jj) * 8 + cgp] = pk2(x.w, y.w);
            }
        }
        __syncthreads();

#pragma unroll
        for (int ch = 0; ch < 2; ch++) {
            u64 acc[4][4];
#pragma unroll
            for (int g = 0; g < 4; g++)
#pragma unroll
                for (int j = 0; j < 4; j++) acc[g][j] = 0ull;

            const u64* zp = zdup + 4 * rg;
            const u64* ep = ctile + (ch * 4) * 8 + cg;
#pragma unroll 8
            for (int l = 0; l < LD; l++) {
                u64 z0 = zp[l * 128 + 0];
                u64 z1 = zp[l * 128 + 1];
                u64 z2 = zp[l * 128 + 2];
                u64 z3 = zp[l * 128 + 3];
                u64 e0 = ep[l * 64 + 0];
                u64 e1 = ep[l * 64 + 8];
                u64 e2 = ep[l * 64 + 16];
                u64 e3 = ep[l * 64 + 24];
                FMA2(acc[0][0], z0, e0); FMA2(acc[0][1], z0, e1);
                FMA2(acc[0][2], z0, e2); FMA2(acc[0][3], z0, e3);
                FMA2(acc[1][0], z1, e0); FMA2(acc[1][1], z1, e1);
                FMA2(acc[1][2], z1, e2); FMA2(acc[1][3], z1, e3);
                FMA2(acc[2][0], z2, e0); FMA2(acc[2][1], z2, e1);
                FMA2(acc[2][2], z2, e2); FMA2(acc[2][3], z2, e3);
                FMA2(acc[3][0], z3, e0); FMA2(acc[3][1], z3, e1);
                FMA2(acc[3][2], z3, e2); FMA2(acc[3][3], z3, e3);
            }

            // Epilogue: d = fl(fl(a + en2) + (-2m)); guarded first-min.
#pragma unroll
            for (int j = 0; j < 4; j++) {
                int k0 = ct * 128 + 16 * cg + 2 * (ch * 4 + j);
                float b0 = sen2[k0], b1 = sen2[k0 + 1];
#pragma unroll
                for (int g = 0; g < 4; g++) {
                    float m0, m1;
                    UNPK2(m0, m1, acc[g][j]);
                    float d0 = __fadd_rn(__fadd_rn(a_g[g], b0),
                                         __fmul_rn(-2.0f, m0));
                    float d1 = __fadd_rn(__fadd_rn(a_g[g], b1),
                                         __fmul_rn(-2.0f, m1));
                    if (d0 < best[g] || (d0 == best[g] && k0 < bi[g])) {
                        best[g] = d0; bi[g] = k0;
                    }
                    if (d1 < best[g] || (d1 == best[g] && k0 + 1 < bi[g])) {
                        best[g] = d1; bi[g] = k0 + 1;
                    }
                }
            }
        }
    }

    // Per-row reduction over 8 code-groups (buffers alias dead ctile).
    __syncthreads();
    float* sredd = (float*)(sm + OFF_RD);
    int*   sredk = (int*)(sm + OFF_RK);
#pragma unroll
    for (int g = 0; g < 4; g++) {
        int r = 4 * rg + g;
        sredd[r * 8 + cg] = best[g];
        sredk[r * 8 + cg] = bi[g];
    }
    __syncthreads();
    if (tid < 128) {
        float bd = __int_as_float(0x7f800000);
        int   bk = 0;
#pragma unroll
        for (int c = 0; c < 8; c++) {
            float d = sredd[tid * 8 + c];
            int   k = sredk[tid * 8 + c];
            if (d < bd || (d == bd && k < bk)) { bd = d; bk = k; }
        }
        int n = rowbase + tid;
        g_idx[n]   = bk;
        out_idx[n] = (float)bk;
    }
}

// ---------------------------------------------------------------------------
// K3: gather z_q (float4), z_q_st = ze + (z_q - ze) in reference op order,
// block-reduce fl32((z_q-ze)^2) in double, one atomicAdd per block.
// ---------------------------------------------------------------------------
__global__ void __launch_bounds__(256)
gather_kernel(const float* __restrict__ ze, const float* __restrict__ emb,
              float* __restrict__ out) {
    __shared__ double swarp[8];
    int i   = (blockIdx.x * 256 + threadIdx.x) * 4;
    int b   = i >> 18;
    int rem = i & 262143;
    int l   = rem >> 12;
    int hw  = rem & 4095;
    int n   = (b << 12) | hw;

    int4   ki  = *(const int4*)(g_idx + n);
    float4 ze4 = *(const float4*)(ze + i);
    float t0 = __fadd_rn(emb[ki.x * LD + l], -ze4.x);
    float t1 = __fadd_rn(emb[ki.y * LD + l], -ze4.y);
    float t2 = __fadd_rn(emb[ki.z * LD + l], -ze4.z);
    float t3 = __fadd_rn(emb[ki.w * LD + l], -ze4.w);
    float4 o4;
    o4.x = __fadd_rn(ze4.x, t0);
    o4.y = __fadd_rn(ze4.y, t1);
    o4.z = __fadd_rn(ze4.z, t2);
    o4.w = __fadd_rn(ze4.w, t3);
    *(float4*)(out + i) = o4;

    double s = (double)__fmul_rn(t0, t0) + (double)__fmul_rn(t1, t1)
             + (double)__fmul_rn(t2, t2) + (double)__fmul_rn(t3, t3);
#pragma unroll
    for (int o = 16; o > 0; o >>= 1)
        s += __shfl_down_sync(0xffffffffu, s, o);
    int w = threadIdx.x >> 5, lid = threadIdx.x & 31;
    if (lid == 0) swarp[w] = s;
    __syncthreads();
    if (w == 0) {
        double v = (lid < 8) ? swarp[lid] : 0.0;
#pragma unroll
        for (int o = 4; o > 0; o >>= 1)
            v += __shfl_down_sync(0xffffffffu, v, o);
        if (lid == 0) atomicAdd(&g_loss, v);
    }
}

__global__ void loss_kernel(float* __restrict__ out) {
    out[ELEMS] = (float)(g_loss / (double)ELEMS * 1.25);
}

// ---------------------------------------------------------------------------
// Launch. Outputs: [z_q_st (4194304)] [loss (1)] [idx (65536)]
// ---------------------------------------------------------------------------
extern "C" void kernel_launch(void* const* d_in, const int* in_sizes, int n_in,
                              void* d_out, int out_size) {
    const float* ze  = (const float*)d_in[0];
    const float* emb = (const float*)d_in[1];
    float* out     = (float*)d_out;
    float* out_idx = out + ELEMS + 1;

    cudaFuncSetAttribute(argmin_kernel,
                         cudaFuncAttributeMaxDynamicSharedMemorySize,
                         SMEM_ARG);

    en2_kernel   <<<(KCODES + 255) / 256, 256>>>(emb);
    argmin_kernel<<<NROWS / 128, 256, SMEM_ARG>>>(ze, emb, out_idx);
    gather_kernel<<<ELEMS / (256 * 4), 256>>>(ze, emb, out);
    loss_kernel  <<<1, 1>>>(out);
}

// round 16
// speedup vs baseline: 4.4722x; 1.1008x over previous
#include <cuda_runtime.h>
#include <cstdint>

// Problem constants
#define LD      64
#define HWD     4096
#define NROWS   65536
#define KCODES  1024
#define ELEMS   4194304
#define LPAD    136         // padded stride (words) -> conflict-free fragment LDS
#define CAND    32          // max candidates per row (overflow -> exact full scan)
#define TAU     2e-3f       // screening slack; bf16 worst-case error ~1.3e-3

#define NBLK_TOTAL 512
#define NBLK_MMA   300      // blocks on the tensor-pipe (screen) path
#define ROWS_MMA   (NBLK_MMA * 128)   // 38400

typedef unsigned long long u64;

// Scratch (static device allocations only)
__device__ int    g_idx[NROWS];
__device__ float  g_en2[KCODES];
__device__ double g_loss;

// ---------------------------------------------------------------------------
// helpers
// ---------------------------------------------------------------------------
__device__ __forceinline__ unsigned fkey(float x) {
    unsigned u = __float_as_uint(x);
    return (u & 0x80000000u) ? ~u : (u | 0x80000000u);
}
__device__ __forceinline__ float funkey(unsigned k) {
    unsigned u = (k & 0x80000000u) ? (k ^ 0x80000000u) : ~k;
    return __uint_as_float(u);
}
__device__ __forceinline__ unsigned pack_bf2(float lo, float hi) {
    unsigned r;
    asm("cvt.rn.bf16x2.f32 %0, %1, %2;" : "=r"(r) : "f"(hi), "f"(lo));
    return r;
}
#define MMA_BF16(c0,c1,c2,c3, a0,a1,a2,a3, b0,b1) \
    asm volatile("mma.sync.aligned.m16n8k16.row.col.f32.bf16.bf16.f32 " \
        "{%0,%1,%2,%3}, {%4,%5,%6,%7}, {%8,%9}, {%0,%1,%2,%3};" \
        : "+f"(c0), "+f"(c1), "+f"(c2), "+f"(c3) \
        : "r"(a0), "r"(a1), "r"(a2), "r"(a3), "r"(b0), "r"(b1))

#define FMA2(d, a, b) \
    asm("fma.rn.f32x2 %0, %1, %2, %0;" : "+l"(d) : "l"(a), "l"(b))
__device__ __forceinline__ u64 pk2(float lo, float hi) {
    u64 r;
    asm("mov.b64 %0, {%1, %2};" : "=l"(r) : "f"(lo), "f"(hi));
    return r;
}
#define UNPK2(lo, hi, in) \
    asm("mov.b64 {%0, %1}, %2;" : "=f"(lo), "=f"(hi) : "l"(in))

// ---------------------------------------------------------------------------
// K1: exact per-code squared norms (separate mul/add, sequential order —
// matches jnp.sum(emb*emb, axis=1) bit-exactly). Zeroes loss accumulator.
// ---------------------------------------------------------------------------
__global__ void en2_kernel(const float* __restrict__ emb) {
    int k = blockIdx.x * blockDim.x + threadIdx.x;
    if (k == 0) g_loss = 0.0;
    if (k < KCODES) {
        const float* e = emb + k * LD;
        float s = 0.0f;
#pragma unroll
        for (int l = 0; l < LD; l++)
            s = __fadd_rn(s, __fmul_rn(e[l], e[l]));
        g_en2[k] = s;
    }
}

// ---------------------------------------------------------------------------
// Path A (tensor pipe): bf16 mma.sync screen + bit-exact fp32 recheck.
// Verbatim R7 structure (measured 74 MACs/cyc/SM eff, rel_err 0.0).
// ---------------------------------------------------------------------------
__device__ __forceinline__ void mma_path(
    unsigned char* smraw, const float* __restrict__ ze,
    const float* __restrict__ emb, float* __restrict__ out_idx, int rowbase) {
    float*    szf     = (float*)smraw;                   // [64][LPAD]
    unsigned* szb     = (unsigned*)(szf + 64 * LPAD);    // [32][LPAD]
    unsigned* scb     = szb + 32 * LPAD;                 // [32][LPAD]
    float*    sen2t   = (float*)(scb + 32 * LPAD);       // [128]
    unsigned* sminkey = (unsigned*)(sen2t + 128);        // [128]
    int*      ccnt    = (int*)(sminkey + 128);           // [128]
    int*      cand    = ccnt + 128;                      // [128][CAND]

    const int tid  = threadIdx.x;
    const int lane = tid & 31, wid = tid >> 5;
    const int b   = rowbase >> 12;
    const int hw0 = rowbase & 4095;

    if (tid < 128) { sminkey[tid] = 0xFFFFFFFFu; ccnt[tid] = 0; }

    for (int i = tid; i < 32 * 128; i += 256) {
        int l2 = i >> 7, r = i & 127;
        float f0 = ze[((size_t)(b * LD + 2 * l2    ) << 12) + hw0 + r];
        float f1 = ze[((size_t)(b * LD + 2 * l2 + 1) << 12) + hw0 + r];
        szf[(2 * l2    ) * LPAD + r] = f0;
        szf[(2 * l2 + 1) * LPAD + r] = f1;
        szb[l2 * LPAD + r] = pack_bf2(f0, f1);
    }
    __syncthreads();

    const int mb = (wid >> 1) << 5;
    const int nh = (wid & 1) << 6;
    const int q  = lane >> 2;
    const int tg = lane & 3;
    const int r0 = mb + q, r1 = r0 + 8, r2 = r0 + 16, r3 = r0 + 24;

    unsigned Af[4][8];
#pragma unroll
    for (int ks = 0; ks < 4; ks++) {
        int p = ks * 8 + tg;
        Af[ks][0] = szb[(p    ) * LPAD + mb + q];
        Af[ks][1] = szb[(p    ) * LPAD + mb + q + 8];
        Af[ks][2] = szb[(p + 4) * LPAD + mb + q];
        Af[ks][3] = szb[(p + 4) * LPAD + mb + q + 8];
        Af[ks][4] = szb[(p    ) * LPAD + mb + q + 16];
        Af[ks][5] = szb[(p    ) * LPAD + mb + q + 24];
        Af[ks][6] = szb[(p + 4) * LPAD + mb + q + 16];
        Af[ks][7] = szb[(p + 4) * LPAD + mb + q + 24];
    }

    for (int ct = 0; ct < 8; ct++) {
        __syncthreads();
        {
            int c = tid & 127, half = tid >> 7;
            const float4* src =
                (const float4*)(emb + ((size_t)(ct * 128 + c)) * LD + half * 32);
#pragma unroll
            for (int j = 0; j < 8; j++) {
                float4 v = src[j];
                int l2 = half * 16 + j * 2;
                scb[(l2    ) * LPAD + c] = pack_bf2(v.x, v.y);
                scb[(l2 + 1) * LPAD + c] = pack_bf2(v.z, v.w);
            }
            if (tid < 128) sen2t[tid] = g_en2[ct * 128 + tid];
        }
        __syncthreads();

        float acc[8][8];
#pragma unroll
        for (int ns = 0; ns < 8; ns++)
#pragma unroll
            for (int j = 0; j < 8; j++) acc[ns][j] = 0.0f;

#pragma unroll
        for (int ks = 0; ks < 4; ks++) {
            int p = ks * 8 + tg;
#pragma unroll
            for (int ns = 0; ns < 8; ns++) {
                int cb = nh + ns * 8;
                unsigned b0 = scb[(p    ) * LPAD + cb + q];
                unsigned b1 = scb[(p + 4) * LPAD + cb + q];
                MMA_BF16(acc[ns][0], acc[ns][1], acc[ns][2], acc[ns][3],
                         Af[ks][0], Af[ks][1], Af[ks][2], Af[ks][3], b0, b1);
                MMA_BF16(acc[ns][4], acc[ns][5], acc[ns][6], acc[ns][7],
                         Af[ks][4], Af[ks][5], Af[ks][6], Af[ks][7], b0, b1);
            }
        }

        float m0 = __int_as_float(0x7f800000), m1 = m0, m2 = m0, m3 = m0;
#pragma unroll
        for (int ns = 0; ns < 8; ns++) {
            int cl = nh + ns * 8 + 2 * tg;
            float e0 = sen2t[cl], e1 = sen2t[cl + 1];
            acc[ns][0] = e0 - 2.0f * acc[ns][0];
            acc[ns][1] = e1 - 2.0f * acc[ns][1];
            acc[ns][2] = e0 - 2.0f * acc[ns][2];
            acc[ns][3] = e1 - 2.0f * acc[ns][3];
            acc[ns][4] = e0 - 2.0f * acc[ns][4];
            acc[ns][5] = e1 - 2.0f * acc[ns][5];
            acc[ns][6] = e0 - 2.0f * acc[ns][6];
            acc[ns][7] = e1 - 2.0f * acc[ns][7];
            m0 = fminf(m0, fminf(acc[ns][0], acc[ns][1]));
            m1 = fminf(m1, fminf(acc[ns][2], acc[ns][3]));
            m2 = fminf(m2, fminf(acc[ns][4], acc[ns][5]));
            m3 = fminf(m3, fminf(acc[ns][6], acc[ns][7]));
        }
        atomicMin(&sminkey[r0], fkey(m0));
        atomicMin(&sminkey[r1], fkey(m1));
        atomicMin(&sminkey[r2], fkey(m2));
        atomicMin(&sminkey[r3], fkey(m3));
        __syncthreads();

        float t0 = funkey(sminkey[r0]) + TAU;
        float t1 = funkey(sminkey[r1]) + TAU;
        float t2 = funkey(sminkey[r2]) + TAU;
        float t3 = funkey(sminkey[r3]) + TAU;
#pragma unroll
        for (int ns = 0; ns < 8; ns++) {
            int k0 = ct * 128 + nh + ns * 8 + 2 * tg;
#pragma unroll
            for (int j = 0; j < 8; j++) {
                int   row = (j < 2) ? r0 : (j < 4) ? r1 : (j < 6) ? r2 : r3;
                float th  = (j < 2) ? t0 : (j < 4) ? t1 : (j < 6) ? t2 : t3;
                if (acc[ns][j] <= th) {
                    int c = atomicAdd(&ccnt[row], 1);
                    if (c < CAND) cand[row * CAND + c] = k0 + (j & 1);
                }
            }
        }
    }
    __syncthreads();

    if (tid < 128) {
        int r = tid;
        float a = 0.0f;
#pragma unroll
        for (int l = 0; l < LD; l++) {
            float v = szf[l * LPAD + r];
            a = __fadd_rn(a, __fmul_rn(v, v));
        }
        float best = __int_as_float(0x7f800000);
        int   bi   = 0;
        int   cnt  = ccnt[r];
        if (cnt <= CAND) {
            for (int j = 0; j < cnt; j++) {
                int k = cand[r * CAND + j];
                const float* e = emb + (size_t)k * LD;
                float m = 0.0f;
#pragma unroll
                for (int l = 0; l < LD; l++)
                    m = __fmaf_rn(szf[l * LPAD + r], __ldg(e + l), m);
                float d = __fadd_rn(__fadd_rn(a, __ldg(&g_en2[k])),
                                    __fmul_rn(-2.0f, m));
                if (d < best || (d == best && k < bi)) { best = d; bi = k; }
            }
        } else {
            for (int k = 0; k < KCODES; k++) {
                const float* e = emb + (size_t)k * LD;
                float m = 0.0f;
#pragma unroll
                for (int l = 0; l < LD; l++)
                    m = __fmaf_rn(szf[l * LPAD + r], __ldg(e + l), m);
                float d = __fadd_rn(__fadd_rn(a, __ldg(&g_en2[k])),
                                    __fmul_rn(-2.0f, m));
                if (d < best) { best = d; bi = k; }
            }
        }
        int n = rowbase + r;
        g_idx[n]   = bi;
        out_idx[n] = (float)bi;
    }
}

// ---------------------------------------------------------------------------
// Path B (fma pipe): exact FFMA2 register-blocked argmin GEMM.
// Verbatim R12 structure (measured 53 MACs/cyc/SM eff, rel_err 0.0).
// ---------------------------------------------------------------------------
#define FOFF_ZD   0
#define FOFF_CT   65536
#define FOFF_EN2  (65536 + 32768)
#define FOFF_SA   (FOFF_EN2 + 4096)
#define FOFF_RD   FOFF_CT
#define FOFF_RK   (FOFF_CT + 4096)

__device__ __forceinline__ void ffma2_path(
    unsigned char* sm, const float* __restrict__ ze,
    const float* __restrict__ emb, float* __restrict__ out_idx, int rowbase) {
    u64*   zdup  = (u64*)(sm + FOFF_ZD);
    u64*   ctile = (u64*)(sm + FOFF_CT);
    float* sen2  = (float*)(sm + FOFF_EN2);
    float* sa    = (float*)(sm + FOFF_SA);

    const int tid = threadIdx.x;
    const int cg  = tid & 7;
    const int rg  = tid >> 3;
    const int b   = rowbase >> 12;
    const int hw0 = rowbase & 4095;

    {
        int r = tid & 127, h = tid >> 7;
        const float* zc = ze + ((size_t)(b * LD + 32 * h) << 12) + hw0 + r;
#pragma unroll
        for (int l = 0; l < 32; l++) {
            float f = zc[(size_t)l << 12];
            zdup[(32 * h + l) * 128 + r] = pk2(f, f);
        }
    }
    for (int i = tid; i < KCODES; i += 256) sen2[i] = g_en2[i];
    __syncthreads();

    if (tid < 128) {
        const float* zcol = (const float*)(zdup + tid);
        float a = 0.0f;
#pragma unroll
        for (int l = 0; l < LD; l++) {
            float v = zcol[l * 256];
            a = __fadd_rn(a, __fmul_rn(v, v));
        }
        sa[tid] = a;
    }
    __syncthreads();

    float a_g[4];
#pragma unroll
    for (int g = 0; g < 4; g++) a_g[g] = sa[4 * rg + g];

    float best[4];
    int   bi[4];
#pragma unroll
    for (int g = 0; g < 4; g++) {
        best[g] = __int_as_float(0x7f800000);
        bi[g]   = 0;
    }

    for (int ct = 0; ct < 8; ct++) {
        __syncthreads();
        {
            int p = tid & 63, qtr = tid >> 6;
            int jj = p & 7, cgp = p >> 3;
            const float4* e0 = (const float4*)(emb +
                               ((size_t)(ct * 128 + 2 * p)) * LD + qtr * 16);
            const float4* e1 = (const float4*)(emb +
                               ((size_t)(ct * 128 + 2 * p + 1)) * LD + qtr * 16);
#pragma unroll
            for (int v = 0; v < 4; v++) {
                float4 x = e0[v];
                float4 y = e1[v];
                int lb = qtr * 16 + v * 4;
                ctile[((lb + 0) * 8 + jj) * 8 + cgp] = pk2(x.x, y.x);
                ctile[((lb + 1) * 8 + jj) * 8 + cgp] = pk2(x.y, y.y);
                ctile[((lb + 2) * 8 + jj) * 8 + cgp] = pk2(x.z, y.z);
                ctile[((lb + 3) * 8 + jj) * 8 + cgp] = pk2(x.w, y.w);
            }
        }
        __syncthreads();

#pragma unroll
        for (int ch = 0; ch < 2; ch++) {
            u64 acc[4][4];
#pragma unroll
            for (int g = 0; g < 4; g++)
#pragma unroll
                for (int j = 0; j < 4; j++) acc[g][j] = 0ull;

            const u64* zp = zdup + 4 * rg;
            const u64* ep = ctile + (ch * 4) * 8 + cg;
#pragma unroll 8
            for (int l = 0; l < LD; l++) {
                u64 z0 = zp[l * 128 + 0];
                u64 z1 = zp[l * 128 + 1];
                u64 z2 = zp[l * 128 + 2];
                u64 z3 = zp[l * 128 + 3];
                u64 e0 = ep[l * 64 + 0];
                u64 e1 = ep[l * 64 + 8];
                u64 e2 = ep[l * 64 + 16];
                u64 e3 = ep[l * 64 + 24];
                FMA2(acc[0][0], z0, e0); FMA2(acc[0][1], z0, e1);
                FMA2(acc[0][2], z0, e2); FMA2(acc[0][3], z0, e3);
                FMA2(acc[1][0], z1, e0); FMA2(acc[1][1], z1, e1);
                FMA2(acc[1][2], z1, e2); FMA2(acc[1][3], z1, e3);
                FMA2(acc[2][0], z2, e0); FMA2(acc[2][1], z2, e1);
                FMA2(acc[2][2], z2, e2); FMA2(acc[2][3], z2, e3);
                FMA2(acc[3][0], z3, e0); FMA2(acc[3][1], z3, e1);
                FMA2(acc[3][2], z3, e2); FMA2(acc[3][3], z3, e3);
            }

#pragma unroll
            for (int j = 0; j < 4; j++) {
                int k0 = ct * 128 + 16 * cg + 2 * (ch * 4 + j);
                float b0 = sen2[k0], b1 = sen2[k0 + 1];
#pragma unroll
                for (int g = 0; g < 4; g++) {
                    float m0, m1;
                    UNPK2(m0, m1, acc[g][j]);
                    float d0 = __fadd_rn(__fadd_rn(a_g[g], b0),
                                         __fmul_rn(-2.0f, m0));
                    float d1 = __fadd_rn(__fadd_rn(a_g[g], b1),
                                         __fmul_rn(-2.0f, m1));
                    if (d0 < best[g] || (d0 == best[g] && k0 < bi[g])) {
                        best[g] = d0; bi[g] = k0;
                    }
                    if (d1 < best[g] || (d1 == best[g] && k0 + 1 < bi[g])) {
                        best[g] = d1; bi[g] = k0 + 1;
                    }
                }
            }
        }
    }

    __syncthreads();
    float* sredd = (float*)(sm + FOFF_RD);
    int*   sredk = (int*)(sm + FOFF_RK);
#pragma unroll
    for (int g = 0; g < 4; g++) {
        int r = 4 * rg + g;
        sredd[r * 8 + cg] = best[g];
        sredk[r * 8 + cg] = bi[g];
    }
    __syncthreads();
    if (tid < 128) {
        float bd = __int_as_float(0x7f800000);
        int   bk = 0;
#pragma unroll
        for (int c = 0; c < 8; c++) {
            float d = sredd[tid * 8 + c];
            int   k = sredk[tid * 8 + c];
            if (d < bd || (d == bd && k < bk)) { bd = d; bk = k; }
        }
        int n = rowbase + tid;
        g_idx[n]   = bk;
        out_idx[n] = (float)bk;
    }
}

// ---------------------------------------------------------------------------
// K2: hybrid — Bresenham-interleaved block types so every SM holds a mix of
// tensor-pipe and fma-pipe blocks concurrently.
// ---------------------------------------------------------------------------
#define SMEM_HYB (FOFF_SA + 512)   // 102912 B (max of both paths)

__global__ void __launch_bounds__(256, 2)
argmin_hybrid(const float* __restrict__ ze, const float* __restrict__ emb,
              float* __restrict__ out_idx) {
    extern __shared__ unsigned char sm[];
    int bid = blockIdx.x;
    int mma_before = (bid * NBLK_MMA) >> 9;          // / NBLK_TOTAL (=512)
    int mma_upto   = ((bid + 1) * NBLK_MMA) >> 9;
    if (mma_upto != mma_before) {
        mma_path(sm, ze, emb, out_idx, mma_before * 128);
    } else {
        ffma2_path(sm, ze, emb, out_idx,
                   ROWS_MMA + (bid - mma_before) * 128);
    }
}

// ---------------------------------------------------------------------------
// K3: gather z_q (float4), z_q_st = ze + (z_q - ze) in reference op order,
// block-reduce fl32((z_q-ze)^2) in double, one atomicAdd per block.
// ---------------------------------------------------------------------------
__global__ void __launch_bounds__(256)
gather_kernel(const float* __restrict__ ze, const float* __restrict__ emb,
              float* __restrict__ out) {
    __shared__ double swarp[8];
    int i   = (blockIdx.x * 256 + threadIdx.x) * 4;
    int b   = i >> 18;
    int rem = i & 262143;
    int l   = rem >> 12;
    int hw  = rem & 4095;
    int n   = (b << 12) | hw;

    int4   ki  = *(const int4*)(g_idx + n);
    float4 ze4 = *(const float4*)(ze + i);
    float t0 = __fadd_rn(emb[ki.x * LD + l], -ze4.x);
    float t1 = __fadd_rn(emb[ki.y * LD + l], -ze4.y);
    float t2 = __fadd_rn(emb[ki.z * LD + l], -ze4.z);
    float t3 = __fadd_rn(emb[ki.w * LD + l], -ze4.w);
    float4 o4;
    o4.x = __fadd_rn(ze4.x, t0);
    o4.y = __fadd_rn(ze4.y, t1);
    o4.z = __fadd_rn(ze4.z, t2);
    o4.w = __fadd_rn(ze4.w, t3);
    *(float4*)(out + i) = o4;

    double s = (double)__fmul_rn(t0, t0) + (double)__fmul_rn(t1, t1)
             + (double)__fmul_rn(t2, t2) + (double)__fmul_rn(t3, t3);
#pragma unroll
    for (int o = 16; o > 0; o >>= 1)
        s += __shfl_down_sync(0xffffffffu, s, o);
    int w = threadIdx.x >> 5, lid = threadIdx.x & 31;
    if (lid == 0) swarp[w] = s;
    __syncthreads();
    if (w == 0) {
        double v = (lid < 8) ? swarp[lid] : 0.0;
#pragma unroll
        for (int o = 4; o > 0; o >>= 1)
            v += __shfl_down_sync(0xffffffffu, v, o);
        if (lid == 0) atomicAdd(&g_loss, v);
    }
}

__global__ void loss_kernel(float* __restrict__ out) {
    out[ELEMS] = (float)(g_loss / (double)ELEMS * 1.25);
}

// ---------------------------------------------------------------------------
// Launch. Outputs: [z_q_st (4194304)] [loss (1)] [idx (65536)]
// ---------------------------------------------------------------------------
extern "C" void kernel_launch(void* const* d_in, const int* in_sizes, int n_in,
                              void* d_out, int out_size) {
    const float* ze  = (const float*)d_in[0];
    const float* emb = (const float*)d_in[1];
    float* out     = (float*)d_out;
    float* out_idx = out + ELEMS + 1;

    cudaFuncSetAttribute(argmin_hybrid,
                         cudaFuncAttributeMaxDynamicSharedMemorySize,
                         SMEM_HYB);

    en2_kernel   <<<(KCODES + 255) / 256, 256>>>(emb);
    argmin_hybrid<<<NBLK_TOTAL, 256, SMEM_HYB>>>(ze, emb, out_idx);
    gather_kernel<<<ELEMS / (256 * 4), 256>>>(ze, emb, out);
    loss_kernel  <<<1, 1>>>(out);
}